// round 5
// baseline (speedup 1.0000x reference)
#include <cuda_runtime.h>
#include <cuda_fp16.h>

#define NPTS 100000
#define CDIM 64

// Scratch (device globals — no allocations allowed in kernel_launch)
__device__ float  g_q[NPTS * CDIM];
__device__ __half g_k[NPTS * CDIM];
__device__ __half g_v[NPTS * CDIM];
__device__ float  g_a[NPTS * CDIM];

typedef unsigned long long u64;

// d = a * b + d (elementwise on packed f32x2) — FFMA2, only reachable via PTX
__device__ __forceinline__ void fma2(u64& d, u64 a, u64 b) {
    asm("fma.rn.f32x2 %0, %1, %2, %0;" : "+l"(d) : "l"(a), "l"(b));
}
__device__ __forceinline__ void unpack2(u64 v, float& lo, float& hi) {
    asm("mov.b64 {%0, %1}, %2;" : "=f"(lo), "=f"(hi) : "l"(v));
}
__device__ __forceinline__ u64 pack2f(float lo, float hi) {
    u64 r;
    asm("mov.b64 %0, {%1, %2};" : "=l"(r) : "f"(lo), "f"(hi));
    return r;
}

// ---------------------------------------------------------------------------
// Kernel 1: fused q/k/v projection.  [N,64] @ [64,192] (Wq|Wk|Wv columns).
// Persistent blocks; W fully resident in smem (k-pair-interleaved so one
// LDS.128 = 2 FFMA2 weight pairs); feats tile duplicated so one broadcast
// LDS.128 = 2 ready multiplier pairs. q stored fp32, k/v stored fp16.
// ---------------------------------------------------------------------------
extern __shared__ float qkv_smem[];

__global__ __launch_bounds__(256, 2) void qkv_kernel(
    const float* __restrict__ feats,
    const float* __restrict__ Wq,
    const float* __restrict__ Wk,
    const float* __restrict__ Wv,
    int N, int ntiles)
{
    float* sFd = qkv_smem;          // 64*64*2 = 8192 floats (32 KB)
    float* sW2 = qkv_smem + 8192;   // 64*192  = 12288 floats (48 KB)

    const int tid = threadIdx.x;
    const int ty  = tid >> 5;   // 0..7 : row group (8 rows each)
    const int tx  = tid & 31;   // 0..31: col pair within each matrix

    // ---- Load W once (k-pair-interleaved layout) ----
    {
        const float* Ws[3] = {Wq, Wk, Wv};
#pragma unroll
        for (int j = 0; j < 3; j++) {
            const float* W = Ws[j];
            for (int t = tid; t < 4096; t += 256) {
                int k = t >> 6, c = t & 63;
                int p = j * 32 + (c >> 1);
                sW2[((k >> 1) * 96 + p) * 4 + (k & 1) * 2 + (c & 1)] = W[t];
            }
        }
    }
    __syncthreads();

    for (int tile = blockIdx.x; tile < ntiles; tile += gridDim.x) {
        const int row0 = tile * 64;
        const int rows = min(64, N - row0);

        // ---- Load feats tile, duplicated ----
        if (rows == 64) {
            const float4* src = (const float4*)(feats + (size_t)row0 * 64);
#pragma unroll
            for (int t = 0; t < 4; t++) {
                int e = tid + 256 * t;
                float4 v = src[e];
                float* d = &sFd[((e >> 4) * 64 + (e & 15) * 4) * 2];
                *(float2*)(d + 0) = make_float2(v.x, v.x);
                *(float2*)(d + 2) = make_float2(v.y, v.y);
                *(float2*)(d + 4) = make_float2(v.z, v.z);
                *(float2*)(d + 6) = make_float2(v.w, v.w);
            }
        } else {
            for (int t = tid; t < 4096; t += 256) {
                int r = t >> 6, c = t & 63;
                float v = (r < rows) ? feats[(size_t)(row0 + r) * 64 + c] : 0.f;
                *(float2*)&sFd[(r * 64 + c) * 2] = make_float2(v, v);
            }
        }
        __syncthreads();

        u64 acc[8][3];
#pragma unroll
        for (int r = 0; r < 8; r++)
#pragma unroll
            for (int j = 0; j < 3; j++) acc[r][j] = 0ull;

#pragma unroll 2
        for (int kk = 0; kk < 32; kk++) {
            ulonglong2 f[8];
#pragma unroll
            for (int r = 0; r < 8; r++)
                f[r] = *(const ulonglong2*)&sFd[((ty * 8 + r) * 64 + kk * 2) * 2];
#pragma unroll
            for (int j = 0; j < 3; j++) {
                ulonglong2 w = *(const ulonglong2*)&sW2[(kk * 96 + j * 32 + tx) * 4];
#pragma unroll
                for (int r = 0; r < 8; r++) {
                    fma2(acc[r][j], w.x, f[r].x);
                    fma2(acc[r][j], w.y, f[r].y);
                }
            }
        }

#pragma unroll
        for (int r = 0; r < 8; r++) {
            int row = row0 + ty * 8 + r;
            if (row < N) {
                size_t off = (size_t)row * 64 + 2 * tx;
                float2 vq, vk, vv;
                unpack2(acc[r][0], vq.x, vq.y);
                unpack2(acc[r][1], vk.x, vk.y);
                unpack2(acc[r][2], vv.x, vv.y);
                *(float2*)&g_q[off]  = vq;
                *(__half2*)&g_k[off] = __float22half2_rn(vk);
                *(__half2*)&g_v[off] = __float22half2_rn(vv);
            }
        }
        __syncthreads();
    }
}

// ---------------------------------------------------------------------------
// Kernel 2: KNN attention. One thread per (point, head).
// Warp = 4 points x 8 heads; neighbor rows are fp16 (128 B/row) so the 8-lane
// head group reads a row fully coalesced with ONE LDG.128 per lane.
// ---------------------------------------------------------------------------
__global__ __launch_bounds__(256) void attn_kernel(const int* __restrict__ knn, int N)
{
    const int g = blockIdx.x * 256 + threadIdx.x;
    int n = g >> 3;
    const int h = g & 7;
    const bool valid = (n < N);
    if (n >= N) n = N - 1;   // clamp: all lanes stay active for shuffles

    const int lane = threadIdx.x & 31;
    const int base = lane & 24;

    const int my0 = knn[(size_t)n * 16 + h * 2];
    const int my1 = knn[(size_t)n * 16 + h * 2 + 1];

    const float* qp = g_q + (size_t)n * 64 + h * 8;
    const float4 q0 = *(const float4*)qp;
    const float4 q1 = *(const float4*)(qp + 4);

    int   idx[16];
    float s[16];
#pragma unroll
    for (int k = 0; k < 16; k++) {
        int v = (k & 1) ? my1 : my0;
        idx[k] = __shfl_sync(0xffffffffu, v, base + (k >> 1));
    }

#pragma unroll
    for (int k = 0; k < 16; k++) {
        const __half2* kp = (const __half2*)(g_k + (size_t)idx[k] * 64 + h * 8);
        uint4 raw = *(const uint4*)kp;   // 8 halves
        float2 a0 = __half22float2(*(__half2*)&raw.x);
        float2 a1 = __half22float2(*(__half2*)&raw.y);
        float2 a2 = __half22float2(*(__half2*)&raw.z);
        float2 a3 = __half22float2(*(__half2*)&raw.w);
        float d = q0.x * a0.x + q0.y * a0.y + q0.z * a1.x + q0.w * a1.y
                + q1.x * a2.x + q1.y * a2.y + q1.z * a3.x + q1.w * a3.y;
        s[k] = d * 0.3535533905932738f;   // 1/sqrt(8)
    }

    // softmax over 16 neighbors (registers)
    float m = s[0];
#pragma unroll
    for (int k = 1; k < 16; k++) m = fmaxf(m, s[k]);
    float sum = 0.f;
#pragma unroll
    for (int k = 0; k < 16; k++) { s[k] = __expf(s[k] - m); sum += s[k]; }
    const float inv = 1.0f / sum;

    float o[8];
#pragma unroll
    for (int d = 0; d < 8; d++) o[d] = 0.f;
#pragma unroll
    for (int k = 0; k < 16; k++) {
        const __half2* vp = (const __half2*)(g_v + (size_t)idx[k] * 64 + h * 8);
        uint4 raw = *(const uint4*)vp;
        float2 a0 = __half22float2(*(__half2*)&raw.x);
        float2 a1 = __half22float2(*(__half2*)&raw.y);
        float2 a2 = __half22float2(*(__half2*)&raw.z);
        float2 a3 = __half22float2(*(__half2*)&raw.w);
        const float p = s[k];
        o[0] += p * a0.x; o[1] += p * a0.y; o[2] += p * a1.x; o[3] += p * a1.y;
        o[4] += p * a2.x; o[5] += p * a2.y; o[6] += p * a3.x; o[7] += p * a3.y;
    }

    if (valid) {
        float4 r0 = make_float4(o[0] * inv, o[1] * inv, o[2] * inv, o[3] * inv);
        float4 r1 = make_float4(o[4] * inv, o[5] * inv, o[6] * inv, o[7] * inv);
        float* op = g_a + (size_t)n * 64 + h * 8;
        *(float4*)op       = r0;
        *(float4*)(op + 4) = r1;
    }
}

// ---------------------------------------------------------------------------
// Kernel 3: output projection. [N,64] @ Wo[64,64] + bo. Register-tiled GEMM.
// ---------------------------------------------------------------------------
__global__ __launch_bounds__(256) void oproj_kernel(
    const float* __restrict__ Wo,
    const float* __restrict__ bo,
    float* __restrict__ out,
    int N)
{
    __shared__ __align__(16) float sF[64 * 64];
    __shared__ __align__(16) float sW[64 * 64];

    const int tid  = threadIdx.x;
    const int row0 = blockIdx.x * 64;

    {
        const float4* src = (const float4*)Wo;
        float4* dst = (float4*)sW;
#pragma unroll
        for (int t = 0; t < 4; t++) dst[tid + 256 * t] = src[tid + 256 * t];
    }
    if (row0 + 64 <= N) {
        const float4* src = (const float4*)(g_a + (size_t)row0 * 64);
        float4* dst = (float4*)sF;
#pragma unroll
        for (int t = 0; t < 4; t++) dst[tid + 256 * t] = src[tid + 256 * t];
    } else {
        for (int t = tid; t < 64 * 64; t += 256) {
            int r = t >> 6;
            sF[t] = (row0 + r < N) ? g_a[(size_t)(row0 + r) * 64 + (t & 63)] : 0.f;
        }
    }
    __syncthreads();

    const int ty = tid >> 5;
    const int tx = tid & 31;

    u64 acc[8];
#pragma unroll
    for (int r = 0; r < 8; r++) acc[r] = 0ull;

#pragma unroll 8
    for (int i = 0; i < 64; i++) {
        u64 w = *(const u64*)&sW[i * 64 + 2 * tx];
#pragma unroll
        for (int r = 0; r < 8; r++) {
            float fv = sF[(ty * 8 + r) * 64 + i];
            fma2(acc[r], w, pack2f(fv, fv));
        }
    }

    const float b0 = bo[2 * tx];
    const float b1 = bo[2 * tx + 1];
#pragma unroll
    for (int r = 0; r < 8; r++) {
        int row = row0 + ty * 8 + r;
        if (row < N) {
            float2 v;
            unpack2(acc[r], v.x, v.y);
            v.x += b0; v.y += b1;
            *(float2*)&out[(size_t)row * 64 + 2 * tx] = v;
        }
    }
}

// ---------------------------------------------------------------------------
extern "C" void kernel_launch(void* const* d_in, const int* in_sizes, int n_in,
                              void* d_out, int out_size)
{
    const float* feats = (const float*)d_in[0];
    const int*   knn   = (const int*)d_in[1];
    const float* Wq    = (const float*)d_in[2];
    const float* Wk    = (const float*)d_in[3];
    const float* Wv    = (const float*)d_in[4];
    const float* Wo    = (const float*)d_in[5];
    const float* bo    = (const float*)d_in[6];
    float* out = (float*)d_out;

    const int N = in_sizes[0] / CDIM;
    const int ntiles = (N + 63) / 64;
    const int attn_blocks = (N * 8 + 255) / 256;
    const int qkv_smem_bytes = (8192 + 12288) * 4;   // 80 KB

    cudaFuncSetAttribute(qkv_kernel, cudaFuncAttributeMaxDynamicSharedMemorySize,
                         qkv_smem_bytes);

    qkv_kernel<<<296, 256, qkv_smem_bytes>>>(feats, Wq, Wk, Wv, N, ntiles);
    attn_kernel<<<attn_blocks, 256>>>(knn, N);
    oproj_kernel<<<ntiles, 256>>>(Wo, bo, out, N);
}

// round 8
// speedup vs baseline: 1.0590x; 1.0590x over previous
#include <cuda_runtime.h>
#include <cuda_fp16.h>
#include <cstdint>

// NOTE (journal): tcgen05/TMEM is UNUSABLE under this harness toolchain — nvcc
// emits PTX at target compute_103 (no 'a'), and ptxas rejects all tcgen05.*
// instructions. Scalar FFMA2 path only.

#define NPTS 100000
#define CDIM 64
#define TILE 64

// Scratch (device globals — no allocations allowed in kernel_launch)
__device__ float  g_q[NPTS * CDIM];
__device__ __half g_k[NPTS * CDIM];
__device__ __half g_v[NPTS * CDIM];

typedef unsigned long long u64;

// d = a * b + d (elementwise on packed f32x2) — FFMA2, only reachable via PTX
__device__ __forceinline__ void fma2(u64& d, u64 a, u64 b) {
    asm("fma.rn.f32x2 %0, %1, %2, %0;" : "+l"(d) : "l"(a), "l"(b));
}
__device__ __forceinline__ void unpack2(u64 v, float& lo, float& hi) {
    asm("mov.b64 {%0, %1}, %2;" : "=f"(lo), "=f"(hi) : "l"(v));
}
__device__ __forceinline__ u64 pack2f(float lo, float hi) {
    u64 r;
    asm("mov.b64 %0, {%1, %2};" : "=l"(r) : "f"(lo), "f"(hi));
    return r;
}

// ---------------------------------------------------------------------------
// Kernel 1: fused q/k/v projection.  [N,64] @ [64,192] (Wq|Wk|Wv columns).
// Persistent blocks; W fully resident in smem (k-pair-interleaved: one LDS.128
// = 2 FFMA2 weight pairs); feats tile DOUBLE-BUFFERED + duplicated ((f,f)
// pairs: one broadcast LDS.128 = 2 ready multiplier pairs).
// Per tile: prefetch next tile's feats (LDG) BEFORE compute, expand into the
// other buffer after, ONE __syncthreads per tile.
// q stored fp32, k/v stored fp16.
// ---------------------------------------------------------------------------
extern __shared__ float qkv_smem[];

__device__ __forceinline__ void expand_tile(float* sFd, const uint4* nf, int tid)
{
    // nf[i] holds float4 #(tid + 256*i) of the 64x64 tile.
#pragma unroll
    for (int i = 0; i < 4; i++) {
        int e = tid + (i << 8);
        float4 v = *(const float4*)&nf[i];
        float* d = &sFd[((e >> 4) * 64 + (e & 15) * 4) * 2];
        *(float2*)(d + 0) = make_float2(v.x, v.x);
        *(float2*)(d + 2) = make_float2(v.y, v.y);
        *(float2*)(d + 4) = make_float2(v.z, v.z);
        *(float2*)(d + 6) = make_float2(v.w, v.w);
    }
}

__device__ __forceinline__ void load_tile_regs(uint4* nf, const float* feats,
                                               int row0, int N, int tid)
{
#pragma unroll
    for (int i = 0; i < 4; i++) {
        int e = tid + (i << 8);
        int row = row0 + (e >> 4);
        if (row < N)
            nf[i] = *(const uint4*)(feats + (size_t)row * 64 + ((e & 15) << 2));
        else
            nf[i] = make_uint4(0u, 0u, 0u, 0u);
    }
}

__global__ __launch_bounds__(256, 2) void qkv_kernel(
    const float* __restrict__ feats,
    const float* __restrict__ Wq,
    const float* __restrict__ Wk,
    const float* __restrict__ Wv,
    int N, int ntiles)
{
    float* sFd0 = qkv_smem;            // 8192 floats (32 KB)
    float* sFd1 = qkv_smem + 8192;     // 8192 floats (32 KB)
    float* sW2  = qkv_smem + 16384;    // 12288 floats (48 KB)

    const int tid = threadIdx.x;
    const int ty  = tid >> 5;   // 0..7 : row group (8 rows each)
    const int tx  = tid & 31;   // 0..31: col pair within each matrix

    // ---- Load W once (k-pair-interleaved layout) ----
    {
        const float* Ws[3] = {Wq, Wk, Wv};
#pragma unroll
        for (int j = 0; j < 3; j++) {
            const float* W = Ws[j];
            for (int t = tid; t < 4096; t += 256) {
                int k = t >> 6, c = t & 63;
                int p = j * 32 + (c >> 1);
                sW2[((k >> 1) * 96 + p) * 4 + (k & 1) * 2 + (c & 1)] = W[t];
            }
        }
    }

    // ---- Prologue: load + expand first tile into buffer 0 ----
    int tile = blockIdx.x;
    if (tile < ntiles) {
        uint4 nf[4];
        load_tile_regs(nf, feats, tile * TILE, N, tid);
        expand_tile(sFd0, nf, tid);
    }
    __syncthreads();

    int cur = 0;
    for (; tile < ntiles; tile += gridDim.x) {
        const int row0 = tile * TILE;
        const int tile_next = tile + gridDim.x;
        const bool has_next = (tile_next < ntiles);
        float* sFd  = cur ? sFd1 : sFd0;
        float* sFdN = cur ? sFd0 : sFd1;

        // ---- Prefetch next tile's feats (latency hidden by compute) ----
        uint4 nf[4];
        if (has_next) load_tile_regs(nf, feats, tile_next * TILE, N, tid);

        // ---- Compute ----
        u64 acc[8][3];
#pragma unroll
        for (int r = 0; r < 8; r++)
#pragma unroll
            for (int j = 0; j < 3; j++) acc[r][j] = 0ull;

#pragma unroll 2
        for (int kk = 0; kk < 32; kk++) {
            ulonglong2 w[3];
#pragma unroll
            for (int j = 0; j < 3; j++)
                w[j] = *(const ulonglong2*)&sW2[(kk * 96 + j * 32 + tx) * 4];
#pragma unroll
            for (int r = 0; r < 8; r++) {
                ulonglong2 f = *(const ulonglong2*)&sFd[((ty * 8 + r) * 64 + kk * 2) * 2];
#pragma unroll
                for (int j = 0; j < 3; j++) {
                    fma2(acc[r][j], w[j].x, f.x);
                    fma2(acc[r][j], w[j].y, f.y);
                }
            }
        }

        // ---- Expand next tile into the other buffer ----
        if (has_next) expand_tile(sFdN, nf, tid);

        // ---- Store outputs ----
#pragma unroll
        for (int r = 0; r < 8; r++) {
            int row = row0 + ty * 8 + r;
            if (row < N) {
                size_t off = (size_t)row * 64 + 2 * tx;
                float2 vq, vk, vv;
                unpack2(acc[r][0], vq.x, vq.y);
                unpack2(acc[r][1], vk.x, vk.y);
                unpack2(acc[r][2], vv.x, vv.y);
                *(float2*)&g_q[off]  = vq;
                *(__half2*)&g_k[off] = __float22half2_rn(vk);
                *(__half2*)&g_v[off] = __float22half2_rn(vv);
            }
        }

        cur ^= 1;
        __syncthreads();   // next buffer fully expanded + current buffer free
    }
}

// ---------------------------------------------------------------------------
// Kernel 2: KNN attention + block-staged output projection.
// Block = 256 threads = 32 points (8 threads/point, one per head).
// Warp = 4 points x 8 heads; fp16 neighbor rows (128 B) fully coalesced.
// Epilogue: stage per-point attention outputs (32x64 fp32, 8KB smem), then an
// oproj-style register-tiled GEMM with Wo resident in smem (16KB): each thread
// computes 4 rows x 1 col-pair with FFMA2. The GEMM issue-work hides under the
// gather phase's idle issue slots (attn was issue=18%).
// ---------------------------------------------------------------------------
__global__ __launch_bounds__(256) void attn_kernel(
    const int* __restrict__ knn,
    const float* __restrict__ Wo,
    const float* __restrict__ bo,
    float* __restrict__ out,
    int N)
{
    __shared__ __align__(16) float sWo[64 * 64];   // 16 KB
    __shared__ __align__(16) float sO[32 * 64];    // 8 KB staging

    const int tid = threadIdx.x;

    // Load Wo into smem (one-time, coalesced)
    {
        const float4* src = (const float4*)Wo;
        float4* dst = (float4*)sWo;
#pragma unroll
        for (int t = 0; t < 4; t++) dst[tid + 256 * t] = src[tid + 256 * t];
    }

    const int g = blockIdx.x * 256 + tid;
    int n = g >> 3;
    const int h = g & 7;
    if (n >= N) n = N - 1;   // clamp: all lanes stay active for shuffles

    const int lane = tid & 31;
    const int base = lane & 24;

    const int my0 = knn[(size_t)n * 16 + h * 2];
    const int my1 = knn[(size_t)n * 16 + h * 2 + 1];

    const float* qp = g_q + (size_t)n * 64 + h * 8;
    const float4 q0 = *(const float4*)qp;
    const float4 q1 = *(const float4*)(qp + 4);

    int   idx[16];
    float s[16];
#pragma unroll
    for (int k = 0; k < 16; k++) {
        int v = (k & 1) ? my1 : my0;
        idx[k] = __shfl_sync(0xffffffffu, v, base + (k >> 1));
    }

#pragma unroll
    for (int k = 0; k < 16; k++) {
        uint4 raw = *(const uint4*)(g_k + (size_t)idx[k] * 64 + h * 8);
        float2 a0 = __half22float2(*(__half2*)&raw.x);
        float2 a1 = __half22float2(*(__half2*)&raw.y);
        float2 a2 = __half22float2(*(__half2*)&raw.z);
        float2 a3 = __half22float2(*(__half2*)&raw.w);
        float d = q0.x * a0.x + q0.y * a0.y + q0.z * a1.x + q0.w * a1.y
                + q1.x * a2.x + q1.y * a2.y + q1.z * a3.x + q1.w * a3.y;
        s[k] = d * 0.3535533905932738f;   // 1/sqrt(8)
    }

    // softmax over 16 neighbors (registers)
    float m = s[0];
#pragma unroll
    for (int k = 1; k < 16; k++) m = fmaxf(m, s[k]);
    float sum = 0.f;
#pragma unroll
    for (int k = 0; k < 16; k++) { s[k] = __expf(s[k] - m); sum += s[k]; }
    const float inv = 1.0f / sum;

    float o[8];
#pragma unroll
    for (int d = 0; d < 8; d++) o[d] = 0.f;
#pragma unroll
    for (int k = 0; k < 16; k++) {
        uint4 raw = *(const uint4*)(g_v + (size_t)idx[k] * 64 + h * 8);
        float2 a0 = __half22float2(*(__half2*)&raw.x);
        float2 a1 = __half22float2(*(__half2*)&raw.y);
        float2 a2 = __half22float2(*(__half2*)&raw.z);
        float2 a3 = __half22float2(*(__half2*)&raw.w);
        const float p = s[k];
        o[0] += p * a0.x; o[1] += p * a0.y; o[2] += p * a1.x; o[3] += p * a1.y;
        o[4] += p * a2.x; o[5] += p * a2.y; o[6] += p * a3.x; o[7] += p * a3.y;
    }

    // ---- Stage this (point, head) slice: sO[p_local][h*8 .. h*8+7] ----
    {
        const int p_local = tid >> 3;
        float* sp = &sO[p_local * 64 + h * 8];
        *(float4*)(sp)     = make_float4(o[0] * inv, o[1] * inv, o[2] * inv, o[3] * inv);
        *(float4*)(sp + 4) = make_float4(o[4] * inv, o[5] * inv, o[6] * inv, o[7] * inv);
    }
    __syncthreads();

    // ---- Block GEMM: out[32,64] = sO[32,64] @ sWo[64,64] + bo ----
    const int ty = tid >> 5;   // 0..7 : 4-row group
    const int tx = tid & 31;   // col pair

    u64 acc[4];
    {
        const float b0 = bo[2 * tx];
        const float b1 = bo[2 * tx + 1];
#pragma unroll
        for (int r = 0; r < 4; r++) acc[r] = pack2f(b0, b1);
    }

#pragma unroll 8
    for (int i = 0; i < 64; i++) {
        u64 w = *(const u64*)&sWo[i * 64 + 2 * tx];
#pragma unroll
        for (int r = 0; r < 4; r++) {
            float fv = sO[(ty * 4 + r) * 64 + i];
            fma2(acc[r], w, pack2f(fv, fv));
        }
    }

    const int row_base = blockIdx.x * 32 + ty * 4;
#pragma unroll
    for (int r = 0; r < 4; r++) {
        int row = row_base + r;
        if (row < N) {
            float2 v;
            unpack2(acc[r], v.x, v.y);
            *(float2*)&out[(size_t)row * 64 + 2 * tx] = v;
        }
    }
}

// ---------------------------------------------------------------------------
extern "C" void kernel_launch(void* const* d_in, const int* in_sizes, int n_in,
                              void* d_out, int out_size)
{
    const float* feats = (const float*)d_in[0];
    const int*   knn   = (const int*)d_in[1];
    const float* Wq    = (const float*)d_in[2];
    const float* Wk    = (const float*)d_in[3];
    const float* Wv    = (const float*)d_in[4];
    const float* Wo    = (const float*)d_in[5];
    const float* bo    = (const float*)d_in[6];
    float* out = (float*)d_out;

    const int N = in_sizes[0] / CDIM;
    const int ntiles = (N + TILE - 1) / TILE;
    const int attn_blocks = (N * 8 + 255) / 256;
    const int qkv_smem_bytes = (8192 * 2 + 12288) * 4;   // 112 KB

    cudaFuncSetAttribute(qkv_kernel, cudaFuncAttributeMaxDynamicSharedMemorySize,
                         qkv_smem_bytes);

    int grid = 296;
    if (grid > ntiles) grid = ntiles;
    qkv_kernel<<<grid, 256, qkv_smem_bytes>>>(feats, Wq, Wk, Wv, N, ntiles);
    attn_kernel<<<attn_blocks, 256>>>(knn, Wo, bo, out, N);
}

// round 9
// speedup vs baseline: 1.3166x; 1.2433x over previous
#include <cuda_runtime.h>
#include <cuda_fp16.h>
#include <cstdint>

// Journal: tcgen05/TMEM unusable (harness emits compute_103 PTX; ptxas rejects
// sm_103a-only instructions). BUT legacy mma.sync (HMMA) IS available — qkv
// now runs on the tensor pipe via m16n8k16 fp16 MMA + split-fp16 (3 terms)
// for fp32-equivalent precision.

#define NPTS 100000
#define CDIM 64
#define TILE 64
#define SK   72   // smem row stride in halves (conflict-free ldmatrix)

// Scratch (device globals — no allocations allowed in kernel_launch)
__device__ float  g_q[NPTS * CDIM];
__device__ __half g_k[NPTS * CDIM];
__device__ __half g_v[NPTS * CDIM];

typedef unsigned long long u64;

__device__ __forceinline__ uint32_t smem_to_u32(const void* p) {
    uint32_t a;
    asm("{ .reg .u64 t; cvta.to.shared.u64 t, %1; cvt.u32.u64 %0, t; }" : "=r"(a) : "l"(p));
    return a;
}
__device__ __forceinline__ void fma2(u64& d, u64 a, u64 b) {
    asm("fma.rn.f32x2 %0, %1, %2, %0;" : "+l"(d) : "l"(a), "l"(b));
}
__device__ __forceinline__ void unpack2(u64 v, float& lo, float& hi) {
    asm("mov.b64 {%0, %1}, %2;" : "=f"(lo), "=f"(hi) : "l"(v));
}
__device__ __forceinline__ u64 pack2f(float lo, float hi) {
    u64 r;
    asm("mov.b64 %0, {%1, %2};" : "=l"(r) : "f"(lo), "f"(hi));
    return r;
}

// ---- HMMA building blocks (sm_80-era PTX, valid on compute_103) ----
__device__ __forceinline__ void ldm_x4(uint32_t* r, uint32_t addr) {
    asm volatile("ldmatrix.sync.aligned.m8n8.x4.shared.b16 {%0,%1,%2,%3}, [%4];"
                 : "=r"(r[0]), "=r"(r[1]), "=r"(r[2]), "=r"(r[3]) : "r"(addr));
}
__device__ __forceinline__ void ldm_x2(uint32_t* r, uint32_t addr) {
    asm volatile("ldmatrix.sync.aligned.m8n8.x2.shared.b16 {%0,%1}, [%2];"
                 : "=r"(r[0]), "=r"(r[1]) : "r"(addr));
}
__device__ __forceinline__ void mma16816(float* c, const uint32_t* a, const uint32_t* b) {
    asm volatile("mma.sync.aligned.m16n8k16.row.col.f32.f16.f16.f32 "
                 "{%0,%1,%2,%3}, {%4,%5,%6,%7}, {%8,%9}, {%0,%1,%2,%3};"
                 : "+f"(c[0]), "+f"(c[1]), "+f"(c[2]), "+f"(c[3])
                 : "r"(a[0]), "r"(a[1]), "r"(a[2]), "r"(a[3]), "r"(b[0]), "r"(b[1]));
}

// fp32 -> (hi, lo) fp16 split: hi + lo ≈ x with ~2^-22 relative error.
__device__ __forceinline__ void split_f16(float x, __half& hi, __half& lo) {
    hi = __float2half_rn(x);
    lo = __float2half_rn(x - __half2float(hi));
}

// ---------------------------------------------------------------------------
// Kernel 1: q/k/v projection on the tensor pipe.
// D[64,192] per tile = feats[64,64] @ (Wq|Wk|Wv), via m16n8k16 fp16 MMA,
// 3-term split-fp16 (fp32-equivalent). Persistent blocks; W^T hi/lo resident
// in smem. Warp = 32 rows x 48 cols = 2 row-tiles x 6 n-tiles; per tile per
// warp: 16 ldmatrix.x4 (A) + 48 ldmatrix.x2 (B) + 144 mma.
// q stored fp32, k/v stored fp16.
// ---------------------------------------------------------------------------
extern __shared__ __align__(16) char qkv_sm[];

__global__ __launch_bounds__(256, 2) void qkv_kernel(
    const float* __restrict__ feats,
    const float* __restrict__ Wq,
    const float* __restrict__ Wk,
    const float* __restrict__ Wv,
    int N, int ntiles)
{
    __half* sAhi = (__half*)qkv_sm;                 // 64*SK halves
    __half* sAlo = sAhi + 64 * SK;
    __half* sWhi = sAlo + 64 * SK;                  // 192*SK halves
    __half* sWlo = sWhi + 192 * SK;

    const uint32_t uBase = smem_to_u32(qkv_sm);
    const uint32_t uAhi = uBase;
    const uint32_t uAlo = uAhi + 64 * SK * 2;
    const uint32_t uWhi = uAlo + 64 * SK * 2;
    const uint32_t uWlo = uWhi + 192 * SK * 2;

    const int tid  = threadIdx.x;
    const int wid  = tid >> 5;
    const int lane = tid & 31;
    const int rg   = wid & 1;    // row group: rows rg*32 .. +32
    const int cg   = wid >> 1;   // col group: cols cg*48 .. +48

    // ---- Convert W (Wq|Wk|Wv) -> W^T [c][k] split-fp16 in smem (once) ----
    {
        const float* Ws[3] = {Wq, Wk, Wv};
        for (int e = tid; e < 12288; e += 256) {
            int c = e >> 6, k = e & 63;
            float w = Ws[c >> 6][(k << 6) + (c & 63)];
            __half hi, lo;
            split_f16(w, hi, lo);
            sWhi[c * SK + k] = hi;
            sWlo[c * SK + k] = lo;
        }
    }
    __syncthreads();

    // Per-thread ldmatrix address offsets (bytes)
    const uint32_t aoff = ((uint32_t)((rg * 32 + (lane & 15)) * SK + ((lane >> 4) << 3))) * 2;
    const uint32_t boff = ((uint32_t)((cg * 48 + (lane & 7)) * SK + (((lane >> 3) & 1) << 3))) * 2;

    for (int tile = blockIdx.x; tile < ntiles; tile += gridDim.x) {
        const int row0 = tile * TILE;

        // ---- feats tile -> split-fp16 smem ----
#pragma unroll
        for (int i = 0; i < 4; i++) {
            int e = tid + (i << 8);
            int r = e >> 4, c4 = (e & 15) << 2;
            float4 v = make_float4(0.f, 0.f, 0.f, 0.f);
            if (row0 + r < N) v = *(const float4*)(feats + (size_t)(row0 + r) * 64 + c4);
            __half h0, l0, h1, l1, h2, l2, h3, l3;
            split_f16(v.x, h0, l0); split_f16(v.y, h1, l1);
            split_f16(v.z, h2, l2); split_f16(v.w, h3, l3);
            __half hbuf[4] = {h0, h1, h2, h3};
            __half lbuf[4] = {l0, l1, l2, l3};
            *(u64*)&sAhi[r * SK + c4] = *(const u64*)hbuf;
            *(u64*)&sAlo[r * SK + c4] = *(const u64*)lbuf;
        }
        __syncthreads();

        // ---- MMA mainloop ----
        float c[2][6][4];
#pragma unroll
        for (int rt = 0; rt < 2; rt++)
#pragma unroll
            for (int nt = 0; nt < 6; nt++)
#pragma unroll
                for (int t = 0; t < 4; t++) c[rt][nt][t] = 0.f;

#pragma unroll
        for (int ks = 0; ks < 4; ks++) {
            uint32_t ahi[2][4], alo[2][4];
#pragma unroll
            for (int rt = 0; rt < 2; rt++) {
                uint32_t off = aoff + (uint32_t)(rt * 16 * SK * 2 + ks * 32);
                ldm_x4(ahi[rt], uAhi + off);
                ldm_x4(alo[rt], uAlo + off);
            }
#pragma unroll
            for (int nt = 0; nt < 6; nt++) {
                uint32_t off = boff + (uint32_t)(nt * 8 * SK * 2 + ks * 32);
                uint32_t bhi[2], blo[2];
                ldm_x2(bhi, uWhi + off);
                ldm_x2(blo, uWlo + off);
#pragma unroll
                for (int rt = 0; rt < 2; rt++) {
                    mma16816(c[rt][nt], ahi[rt], bhi);
                    mma16816(c[rt][nt], alo[rt], bhi);
                    mma16816(c[rt][nt], ahi[rt], blo);
                }
            }
        }
        __syncthreads();   // A buffer free before next tile's store

        // ---- Epilogue: C fragments -> g_q (fp32), g_k/g_v (fp16) ----
#pragma unroll
        for (int rt = 0; rt < 2; rt++) {
            const int r0 = row0 + rg * 32 + rt * 16 + (lane >> 2);
            const int r1 = r0 + 8;
#pragma unroll
            for (int nt = 0; nt < 6; nt++) {
                const int cglob = cg * 48 + nt * 8 + ((lane & 3) << 1);
                const float* cc = c[rt][nt];
                if (cglob < 64) {
                    if (r0 < N) *(float2*)&g_q[(size_t)r0 * 64 + cglob] = make_float2(cc[0], cc[1]);
                    if (r1 < N) *(float2*)&g_q[(size_t)r1 * 64 + cglob] = make_float2(cc[2], cc[3]);
                } else if (cglob < 128) {
                    const int cl = cglob - 64;
                    if (r0 < N) *(__half2*)&g_k[(size_t)r0 * 64 + cl] = __floats2half2_rn(cc[0], cc[1]);
                    if (r1 < N) *(__half2*)&g_k[(size_t)r1 * 64 + cl] = __floats2half2_rn(cc[2], cc[3]);
                } else {
                    const int cl = cglob - 128;
                    if (r0 < N) *(__half2*)&g_v[(size_t)r0 * 64 + cl] = __floats2half2_rn(cc[0], cc[1]);
                    if (r1 < N) *(__half2*)&g_v[(size_t)r1 * 64 + cl] = __floats2half2_rn(cc[2], cc[3]);
                }
            }
        }
    }
}

// ---------------------------------------------------------------------------
// Kernel 2: KNN attention + block-staged output projection (unchanged R8).
// ---------------------------------------------------------------------------
__global__ __launch_bounds__(256) void attn_kernel(
    const int* __restrict__ knn,
    const float* __restrict__ Wo,
    const float* __restrict__ bo,
    float* __restrict__ out,
    int N)
{
    __shared__ __align__(16) float sWo[64 * 64];   // 16 KB
    __shared__ __align__(16) float sO[32 * 64];    // 8 KB staging

    const int tid = threadIdx.x;

    {
        const float4* src = (const float4*)Wo;
        float4* dst = (float4*)sWo;
#pragma unroll
        for (int t = 0; t < 4; t++) dst[tid + 256 * t] = src[tid + 256 * t];
    }

    const int g = blockIdx.x * 256 + tid;
    int n = g >> 3;
    const int h = g & 7;
    if (n >= N) n = N - 1;   // clamp: all lanes stay active for shuffles

    const int lane = tid & 31;
    const int base = lane & 24;

    const int my0 = knn[(size_t)n * 16 + h * 2];
    const int my1 = knn[(size_t)n * 16 + h * 2 + 1];

    const float* qp = g_q + (size_t)n * 64 + h * 8;
    const float4 q0 = *(const float4*)qp;
    const float4 q1 = *(const float4*)(qp + 4);

    int   idx[16];
    float s[16];
#pragma unroll
    for (int k = 0; k < 16; k++) {
        int v = (k & 1) ? my1 : my0;
        idx[k] = __shfl_sync(0xffffffffu, v, base + (k >> 1));
    }

#pragma unroll
    for (int k = 0; k < 16; k++) {
        uint4 raw = *(const uint4*)(g_k + (size_t)idx[k] * 64 + h * 8);
        float2 a0 = __half22float2(*(__half2*)&raw.x);
        float2 a1 = __half22float2(*(__half2*)&raw.y);
        float2 a2 = __half22float2(*(__half2*)&raw.z);
        float2 a3 = __half22float2(*(__half2*)&raw.w);
        float d = q0.x * a0.x + q0.y * a0.y + q0.z * a1.x + q0.w * a1.y
                + q1.x * a2.x + q1.y * a2.y + q1.z * a3.x + q1.w * a3.y;
        s[k] = d * 0.3535533905932738f;   // 1/sqrt(8)
    }

    float m = s[0];
#pragma unroll
    for (int k = 1; k < 16; k++) m = fmaxf(m, s[k]);
    float sum = 0.f;
#pragma unroll
    for (int k = 0; k < 16; k++) { s[k] = __expf(s[k] - m); sum += s[k]; }
    const float inv = 1.0f / sum;

    float o[8];
#pragma unroll
    for (int d = 0; d < 8; d++) o[d] = 0.f;
#pragma unroll
    for (int k = 0; k < 16; k++) {
        uint4 raw = *(const uint4*)(g_v + (size_t)idx[k] * 64 + h * 8);
        float2 a0 = __half22float2(*(__half2*)&raw.x);
        float2 a1 = __half22float2(*(__half2*)&raw.y);
        float2 a2 = __half22float2(*(__half2*)&raw.z);
        float2 a3 = __half22float2(*(__half2*)&raw.w);
        const float p = s[k];
        o[0] += p * a0.x; o[1] += p * a0.y; o[2] += p * a1.x; o[3] += p * a1.y;
        o[4] += p * a2.x; o[5] += p * a2.y; o[6] += p * a3.x; o[7] += p * a3.y;
    }

    {
        const int p_local = tid >> 3;
        float* sp = &sO[p_local * 64 + h * 8];
        *(float4*)(sp)     = make_float4(o[0] * inv, o[1] * inv, o[2] * inv, o[3] * inv);
        *(float4*)(sp + 4) = make_float4(o[4] * inv, o[5] * inv, o[6] * inv, o[7] * inv);
    }
    __syncthreads();

    const int ty = tid >> 5;
    const int tx = tid & 31;

    u64 acc[4];
    {
        const float b0 = bo[2 * tx];
        const float b1 = bo[2 * tx + 1];
#pragma unroll
        for (int r = 0; r < 4; r++) acc[r] = pack2f(b0, b1);
    }

#pragma unroll 8
    for (int i = 0; i < 64; i++) {
        u64 w = *(const u64*)&sWo[i * 64 + 2 * tx];
#pragma unroll
        for (int r = 0; r < 4; r++) {
            float fv = sO[(ty * 4 + r) * 64 + i];
            fma2(acc[r], w, pack2f(fv, fv));
        }
    }

    const int row_base = blockIdx.x * 32 + ty * 4;
#pragma unroll
    for (int r = 0; r < 4; r++) {
        int row = row_base + r;
        if (row < N) {
            float2 v;
            unpack2(acc[r], v.x, v.y);
            *(float2*)&out[(size_t)row * 64 + 2 * tx] = v;
        }
    }
}

// ---------------------------------------------------------------------------
extern "C" void kernel_launch(void* const* d_in, const int* in_sizes, int n_in,
                              void* d_out, int out_size)
{
    const float* feats = (const float*)d_in[0];
    const int*   knn   = (const int*)d_in[1];
    const float* Wq    = (const float*)d_in[2];
    const float* Wk    = (const float*)d_in[3];
    const float* Wv    = (const float*)d_in[4];
    const float* Wo    = (const float*)d_in[5];
    const float* bo    = (const float*)d_in[6];
    float* out = (float*)d_out;

    const int N = in_sizes[0] / CDIM;
    const int ntiles = (N + TILE - 1) / TILE;
    const int attn_blocks = (N * 8 + 255) / 256;
    // smem: A hi/lo 2*64*72*2B + W hi/lo 2*192*72*2B = 18432 + 55296 = 73728 B
    const int qkv_smem_bytes = (64 * SK * 2 + 192 * SK * 2) * 2;

    cudaFuncSetAttribute(qkv_kernel, cudaFuncAttributeMaxDynamicSharedMemorySize,
                         qkv_smem_bytes);

    int grid = 296;
    if (grid > ntiles) grid = ntiles;
    qkv_kernel<<<grid, 256, qkv_smem_bytes>>>(feats, Wq, Wk, Wv, N, ntiles);
    attn_kernel<<<attn_blocks, 256>>>(knn, Wo, bo, out, N);
}